// round 8
// baseline (speedup 1.0000x reference)
#include <cuda_runtime.h>

// FD_discretizer: fused, x-pair coarsened (KX=2) with float2 column loads.
// Block 16x16 threads; each thread -> 2 adjacent outputs (even io).
// 4-col tap window = two aligned float2 per row per field; conflict-free LDS.64.
// Identities: obm == ebm[interior]; interior ext == raw uvp.

#define NXg 1024
#define NYg 1024
#define EX  1026
#define EY  1026
#define NN  (NXg*NYg)

#define PRESS_E (513*EX + 513)

#define BDX 16
#define BDY 16
#define NTHR (BDX*BDY)           // 256
#define OUT_W 32
#define OUT_H 16
#define EXT_W 34
#define EXT_H 18
#define TILE  (EXT_W * EXT_H)    // 612
#define W2    (EXT_W/2)          // 17 float2 per row

__device__ __forceinline__ int clampi(int x, int lo, int hi) {
    return x < lo ? lo : (x > hi ? hi : x);
}
__device__ __forceinline__ int eidx(int je, int ie) {
    return clampi(je - 1, 0, NYg - 1) * NXg + clampi(ie - 1, 0, NXg - 1);
}

struct F3 { float x, y, z; };

__device__ __forceinline__ void dummy_uv(const float* __restrict__ uvp,
                                         const float* __restrict__ ny,
                                         int m, float& du, float& dv) {
    int io = m % NXg;
    int jo = m / NXg;
    bool bc = (io == 0) || (io != NXg - 1 && (jo == 0 || jo == NYg - 1));
    if (bc) { du = ny[3*m]; dv = ny[3*m+1]; }
    else    { du = uvp[3*m]; dv = uvp[3*m+1]; }
}
__device__ __forceinline__ float dummy_p(const float* __restrict__ uvp, int m) {
    int io = m % NXg;
    return (io == NXg - 1) ? 0.0f : uvp[3*m+2];
}

__device__ __forceinline__ F3 ghost_pmask(const float* __restrict__ f,
                                          const float* __restrict__ ny,
                                          int m1, int m2) {
    F3 r;
    float du, dv; dummy_uv(f, ny, m1, du, dv);
    r.x = 2.0f*du - f[3*m2];
    r.y = 2.0f*dv - f[3*m2+1];
    r.z = f[3*m2+2];
    return r;
}
__device__ __forceinline__ F3 ghost_uvmask(const float* __restrict__ f,
                                           int m1, int m2) {
    F3 r;
    float dp = dummy_p(f, m1);
    r.x = f[3*m2];
    r.y = f[3*m2+1];
    r.z = 2.0f*dp - f[3*m2+2];
    return r;
}
__device__ __forceinline__ F3 load3(const float* __restrict__ f, int m) {
    F3 r; r.x = f[3*m]; r.y = f[3*m+1]; r.z = f[3*m+2]; return r;
}

__device__ __forceinline__ void ext_pair(const float* __restrict__ uvp,
                                         const float* __restrict__ old_,
                                         const float* __restrict__ ny,
                                         int je, int ie, F3& en, F3& eo) {
    bool jin = (je >= 1) & (je <= EY - 2);
    if (ie == 0 && jin) {
        int m1 = eidx(je, 1), m2 = eidx(je, 2);
        en = ghost_pmask(uvp, ny, m1, m2);
        eo = ghost_pmask(old_, ny, m1, m2);
    } else if (ie == EX - 1 && jin) {
        int m1 = eidx(je, EX - 2), m2 = eidx(je, EX - 3);
        en = ghost_uvmask(uvp, m1, m2);
        eo = ghost_uvmask(old_, m1, m2);
    } else if (je == 0 && ie >= 1 && ie <= EX - 2) {
        int m1 = eidx(1, ie), m2 = eidx(2, ie);
        en = ghost_pmask(uvp, ny, m1, m2);
        eo = ghost_pmask(old_, ny, m1, m2);
    } else if (je == EY - 1 && ie >= 1 && ie <= EX - 2) {
        int m1 = eidx(EY - 2, ie), m2 = eidx(EY - 3, ie);
        en = ghost_pmask(uvp, ny, m1, m2);
        eo = ghost_pmask(old_, ny, m1, m2);
    } else {
        int m = eidx(je, ie);
        en = load3(uvp, m);
        eo = load3(old_, m);
    }
}

// Load a 4-col window (2 aligned float2) of one row into w[0..3].
#define WIN(ARR, R2, w) do {                                   \
        float2 t0_ = (ARR)[R2], t1_ = (ARR)[(R2) + 1];         \
        (w)[0] = t0_.x; (w)[1] = t0_.y; (w)[2] = t1_.x; (w)[3] = t1_.y; \
    } while (0)

__global__ void __launch_bounds__(NTHR, 5)
fused_kernel(const float* __restrict__ ouv,
             const float* __restrict__ ouv_old,
             const float* __restrict__ ny,
             const float* __restrict__ ebm,
             const float* __restrict__ dtg,
             const float* __restrict__ theta,
             const float* __restrict__ relp,
             float* __restrict__ out) {
    __shared__ float2 s_eu [TILE/2];
    __shared__ float2 s_ev [TILE/2];
    __shared__ float2 s_ep [TILE/2];
    __shared__ float2 s_eou[TILE/2];
    __shared__ float2 s_eov[TILE/2];
    __shared__ float2 s_U  [TILE/2];
    __shared__ float2 s_V  [TILE/2];
    __shared__ float2 s_Uo [TILE/2];
    __shared__ float2 s_Vo [TILE/2];
    __shared__ float2 s_a11[TILE/2];
    __shared__ float2 s_a22[TILE/2];
    __shared__ float2 s_pxx[TILE/2];
    __shared__ float2 s_pxy[TILE/2];
    __shared__ float2 s_pex[TILE/2];
    __shared__ float2 s_pey[TILE/2];
    __shared__ float2 s_rJ [TILE/2];

    const int bx = blockIdx.x, by = blockIdx.y;
    const int lx = threadIdx.x, ly = threadIdx.y;
    const int tid = ly * BDX + lx;

    // ---- cooperative fill of extended tile (scalar view) ----
    for (int s = tid; s < TILE; s += NTHR) {
        int ly2 = s / EXT_W;
        int lx2 = s - ly2 * EXT_W;
        int ie = bx * OUT_W + lx2;
        int je = by * OUT_H + ly2;

        F3 en, eo;
        ext_pair(ouv, ouv_old, ny, je, ie, en, eo);
        int e = je * EX + ie;
        if (e == PRESS_E) en.z = 0.0f;

        float dxx = ebm[5*e + 0];
        float dxy = ebm[5*e + 1];
        float dex = ebm[5*e + 2];
        float dey = ebm[5*e + 3];
        float Jm  = ebm[5*e + 4];
        float rJ  = __fdividef(1.0f, Jm);
        float pq  = en.z * rJ;

        ((float*)s_eu )[s] = en.x;
        ((float*)s_ev )[s] = en.y;
        ((float*)s_ep )[s] = en.z;
        ((float*)s_eou)[s] = eo.x;
        ((float*)s_eov)[s] = eo.y;
        ((float*)s_U  )[s] = (en.x*dxx + en.y*dxy) * rJ;
        ((float*)s_V  )[s] = (en.x*dex + en.y*dey) * rJ;
        ((float*)s_Uo )[s] = (eo.x*dxx + eo.y*dxy) * rJ;
        ((float*)s_Vo )[s] = (eo.x*dex + eo.y*dey) * rJ;
        ((float*)s_a11)[s] = (dxx*dxx + dxy*dxy) * rJ;
        ((float*)s_a22)[s] = (dex*dex + dey*dey) * rJ;
        ((float*)s_pxx)[s] = pq * dxx;
        ((float*)s_pxy)[s] = pq * dxy;
        ((float*)s_pex)[s] = pq * dex;
        ((float*)s_pey)[s] = pq * dey;
        ((float*)s_rJ )[s] = rJ;
    }
    __syncthreads();

    // ---- per-thread pair of outputs ----
    const float rdt   = __fdividef(1.0f, __ldg(dtg));
    const float uc    = __ldg(theta + 0);
    const float cc    = __ldg(theta + 1);
    const float convc = __ldg(theta + 2);
    const float pc    = __ldg(theta + 3);
    const float dc    = __ldg(theta + 4);
    const float relax = __ldg(relp);
    const float cn = convc * (1.0f - relax);
    const float co = convc * relax;

    const int io0 = bx * OUT_W + 2 * lx;      // even
    const int jo  = by * OUT_H + ly;

    // float2 row bases: rows D=ly, C=ly+1, U=ly+2; window f2 cols lx, lx+1
    const int rD = ly * W2 + lx;
    const int rC = rD + W2;
    const int rU = rC + W2;

    float momu[2], momv[2], visu[2], visv[2], visp[2], lossv[2];
    float euK[2], evK[2];   // center eu/ev kept for unsteady

    // -------- group 1: U (row C) + V (rows D,C,U) : continuity; kept for conv-new
    float UC[4], VD[4], VC[4], VU[4];
    WIN(s_U, rC, UC);
    WIN(s_V, rD, VD); WIN(s_V, rC, VC); WIN(s_V, rU, VU);
    #pragma unroll
    for (int q = 0; q < 2; q++) {
        int k = q + 1;
        lossv[q] = 0.5f * ((UC[k+1] - UC[k-1]) + (VU[k] - VD[k])) * cc;
    }

    // -------- group 2: eu windows + a11/a22 : conv-new-u, dif-u, vis-u
    {
        float euD[4], euC[4], euU[4];
        WIN(s_eu, rD, euD); WIN(s_eu, rC, euC); WIN(s_eu, rU, euU);
        float a11C[4], a22D[4], a22C[4], a22U[4];
        WIN(s_a11, rC, a11C);
        WIN(s_a22, rD, a22D); WIN(s_a22, rC, a22C); WIN(s_a22, rU, a22U);

        #pragma unroll
        for (int q = 0; q < 2; q++) {
            int k = q + 1;
            float cnu = 0.25f * ((euC[k] + euC[k+1]) * (UC[k] + UC[k+1])
                               - (euC[k-1] + euC[k]) * (UC[k-1] + UC[k]))
                      + 0.25f * ((euC[k] + euU[k]) * (VC[k] + VU[k])
                               - (euD[k] + euC[k]) * (VD[k] + VC[k]));
            float difu = 0.5f * ((a11C[k] + a11C[k+1]) * (euC[k+1] - euC[k])
                               - (a11C[k-1] + a11C[k]) * (euC[k] - euC[k-1]))
                       + 0.5f * ((a22C[k] + a22U[k]) * (euU[k] - euC[k])
                               - (a22D[k] + a22C[k]) * (euC[k] - euD[k]));
            const float sw = 1.0f / 16.0f;
            visu[q] = sw * (4.0f*euC[k] + 2.0f*(euC[k-1] + euC[k+1] + euD[k] + euU[k])
                            + (euD[k-1] + euD[k+1] + euU[k-1] + euU[k+1]));
            momu[q] = cn * cnu - dc * difu;
            euK[q] = euC[k];
        }

        // -------- group 3: ev windows (a11/a22, U/V reused) : conv-new-v, dif-v, vis-v
        float evD[4], evC[4], evU[4];
        WIN(s_ev, rD, evD); WIN(s_ev, rC, evC); WIN(s_ev, rU, evU);
        #pragma unroll
        for (int q = 0; q < 2; q++) {
            int k = q + 1;
            float cnv = 0.25f * ((evC[k] + evC[k+1]) * (UC[k] + UC[k+1])
                               - (evC[k-1] + evC[k]) * (UC[k-1] + UC[k]))
                      + 0.25f * ((evC[k] + evU[k]) * (VC[k] + VU[k])
                               - (evD[k] + evC[k]) * (VD[k] + VC[k]));
            float difv = 0.5f * ((a11C[k] + a11C[k+1]) * (evC[k+1] - evC[k])
                               - (a11C[k-1] + a11C[k]) * (evC[k] - evC[k-1]))
                       + 0.5f * ((a22C[k] + a22U[k]) * (evU[k] - evC[k])
                               - (a22D[k] + a22C[k]) * (evC[k] - evD[k]));
            const float sw = 1.0f / 16.0f;
            visv[q] = sw * (4.0f*evC[k] + 2.0f*(evC[k-1] + evC[k+1] + evD[k] + evU[k])
                            + (evD[k-1] + evD[k+1] + evU[k-1] + evU[k+1]));
            momv[q] = cn * cnv - dc * difv;
            evK[q] = evC[k];
        }
    }

    // -------- group 4/5: old fields : conv-old + unsteady
    {
        float UoC[4], VoD[4], VoC[4], VoU[4];
        WIN(s_Uo, rC, UoC);
        WIN(s_Vo, rD, VoD); WIN(s_Vo, rC, VoC); WIN(s_Vo, rU, VoU);
        float ouD[4], ouC[4], ouU[4];
        WIN(s_eou, rD, ouD); WIN(s_eou, rC, ouC); WIN(s_eou, rU, ouU);
        float2 rJ2 = s_rJ[rC + ((2*lx + 1) >> 1)];  // f2 holding cols (2lx, 2lx+1)? see below
        // cols 2lx+1, 2lx+2 straddle f2s: load both
        float rJw[4];
        WIN(s_rJ, rC, rJw);

        #pragma unroll
        for (int q = 0; q < 2; q++) {
            int k = q + 1;
            float cou = 0.25f * ((ouC[k] + ouC[k+1]) * (UoC[k] + UoC[k+1])
                               - (ouC[k-1] + ouC[k]) * (UoC[k-1] + UoC[k]))
                      + 0.25f * ((ouC[k] + ouU[k]) * (VoC[k] + VoU[k])
                               - (ouD[k] + ouC[k]) * (VoD[k] + VoC[k]));
            float inv = rJw[k] * rdt;
            momu[q] += co * cou + uc * (euK[q] - ouC[k]) * inv;
        }

        float ovD[4], ovC[4], ovU[4];
        WIN(s_eov, rD, ovD); WIN(s_eov, rC, ovC); WIN(s_eov, rU, ovU);
        #pragma unroll
        for (int q = 0; q < 2; q++) {
            int k = q + 1;
            float cov = 0.25f * ((ovC[k] + ovC[k+1]) * (UoC[k] + UoC[k+1])
                               - (ovC[k-1] + ovC[k]) * (UoC[k-1] + UoC[k]))
                      + 0.25f * ((ovC[k] + ovU[k]) * (VoC[k] + VoU[k])
                               - (ovD[k] + ovC[k]) * (VoD[k] + VoC[k]));
            float inv = rJw[k] * rdt;
            momv[q] += co * cov + uc * (evK[q] - ovC[k]) * inv;
        }
    }

    // -------- group 7: ep windows : vis-p
    {
        float epD[4], epC[4], epU[4];
        WIN(s_ep, rD, epD); WIN(s_ep, rC, epC); WIN(s_ep, rU, epU);
        #pragma unroll
        for (int q = 0; q < 2; q++) {
            int k = q + 1;
            const float sw = 1.0f / 16.0f;
            visp[q] = sw * (4.0f*epC[k] + 2.0f*(epC[k-1] + epC[k+1] + epD[k] + epU[k])
                            + (epD[k-1] + epD[k+1] + epU[k-1] + epU[k+1]));
        }
    }

    // -------- group 8: pressure gradient
    {
        float pxxC[4], pxyC[4], pexD[4], pexU[4], peyD[4], peyU[4];
        WIN(s_pxx, rC, pxxC); WIN(s_pxy, rC, pxyC);
        WIN(s_pex, rD, pexD); WIN(s_pex, rU, pexU);
        WIN(s_pey, rD, peyD); WIN(s_pey, rU, peyU);
        #pragma unroll
        for (int q = 0; q < 2; q++) {
            int k = q + 1;
            float gPx = 0.5f * (pxxC[k+1] - pxxC[k-1]) + 0.5f * (pexU[k] - pexD[k]);
            float gPy = 0.5f * (peyU[k] - peyD[k]) + 0.5f * (pxyC[k+1] - pxyC[k-1]);
            momu[q] += pc * gPx;
            momv[q] += pc * gPy;
        }
    }

    // -------- vectorized stores (io0 even -> 8B aligned) --------
    const int o0 = jo * NXg + io0;
    *(float2*)(out + o0)            = make_float2(lossv[0], lossv[1]);
    *(float2*)(out + NN + o0)       = make_float2(momu[0], momu[1]);
    *(float2*)(out + 2*NN + o0)     = make_float2(momv[0], momv[1]);
    float* vb = out + 3*NN + 3*o0;
    *(float2*)(vb)     = make_float2(visu[0], visv[0]);
    *(float2*)(vb + 2) = make_float2(visp[0], visu[1]);
    *(float2*)(vb + 4) = make_float2(visv[1], visp[1]);
}

extern "C" void kernel_launch(void* const* d_in, const int* in_sizes, int n_in,
                              void* d_out, int out_size) {
    const float* ouv     = (const float*)d_in[0];
    const float* ouv_old = (const float*)d_in[1];
    const float* ny      = (const float*)d_in[2];
    // d_in[3] (obm) unused: obm == ebm[interior]
    const float* ebm     = (const float*)d_in[4];
    const float* dtg     = (const float*)d_in[5];
    const float* theta   = (const float*)d_in[6];
    const float* relp    = (const float*)d_in[7];
    float* out = (float*)d_out;

    dim3 block(BDX, BDY);
    dim3 grid(NXg / OUT_W, NYg / OUT_H);
    fused_kernel<<<grid, block>>>(ouv, ouv_old, ny, ebm, dtg, theta, relp, out);
}

// round 9
// speedup vs baseline: 1.1702x; 1.1702x over previous
#include <cuda_runtime.h>

// FD_discretizer: warp-strip marching stencil, zero shared memory.
// Each warp: 32-column strip (30 outputs), marches H=16 rows in y.
// Derived row values in registers; x-neighbors via warp shuffles.
// Identities: obm == ebm[interior]; interior ext == raw uvp; ep_old unused.

#define NXg 1024
#define NYg 1024
#define EX  1026
#define EY  1026
#define NN  (NXg*NYg)

#define PRESS_E (513*EX + 513)

#define H       16
#define NSTRIP  35           // ceil(1024/30)
#define NCHUNK  64           // 1024/H
#define NWARP   (NSTRIP*NCHUNK)   // 2240
#define BLK     128
#define GRID    (NWARP*32/BLK)    // 560

__device__ __forceinline__ int clampi(int x, int lo, int hi) {
    return x < lo ? lo : (x > hi ? hi : x);
}
__device__ __forceinline__ int eidx(int je, int ie) {
    return clampi(je - 1, 0, NYg - 1) * NXg + clampi(ie - 1, 0, NXg - 1);
}

struct F3 { float x, y, z; };

struct Derived {
    float eu, ev, ep, eou, eov;
    float U, V, Uo, Vo;
    float a11, a22, pxx, pxy, pex, pey, rJ;
};

__device__ __forceinline__ void dummy_uv(const float* __restrict__ uvp,
                                         const float* __restrict__ ny,
                                         int m, float& du, float& dv) {
    int io = m % NXg;
    int jo = m / NXg;
    bool bc = (io == 0) || (io != NXg - 1 && (jo == 0 || jo == NYg - 1));
    if (bc) { du = ny[3*m]; dv = ny[3*m+1]; }
    else    { du = uvp[3*m]; dv = uvp[3*m+1]; }
}
__device__ __forceinline__ float dummy_p(const float* __restrict__ uvp, int m) {
    int io = m % NXg;
    return (io == NXg - 1) ? 0.0f : uvp[3*m+2];
}

__device__ __forceinline__ Derived load_row(
    const float* __restrict__ ouv, const float* __restrict__ ouv_old,
    const float* __restrict__ ny,  const float* __restrict__ ebm,
    int je, int ie)
{
    F3 en; float eox, eoy;
    bool jin = (je >= 1) & (je <= EY - 2);
    if (ie == 0 && jin) {                       // left ghost: INFLOW -> pmask
        int m1 = eidx(je, 1), m2 = eidx(je, 2);
        float du, dv; dummy_uv(ouv, ny, m1, du, dv);
        en.x = 2.0f*du - ouv[3*m2];
        en.y = 2.0f*dv - ouv[3*m2+1];
        en.z = ouv[3*m2+2];
        float duo, dvo; dummy_uv(ouv_old, ny, m1, duo, dvo);
        eox = 2.0f*duo - ouv_old[3*m2];
        eoy = 2.0f*dvo - ouv_old[3*m2+1];
    } else if (ie == EX - 1 && jin) {           // right ghost: OUTFLOW -> uvmask
        int m1 = eidx(je, EX - 2), m2 = eidx(je, EX - 3);
        float dp = dummy_p(ouv, m1);
        en.x = ouv[3*m2];
        en.y = ouv[3*m2+1];
        en.z = 2.0f*dp - ouv[3*m2+2];
        eox = ouv_old[3*m2];
        eoy = ouv_old[3*m2+1];
    } else if (je == 0 && ie >= 1 && ie <= EX - 2) {   // bottom ghost: WALL
        int m1 = eidx(1, ie), m2 = eidx(2, ie);
        float du, dv; dummy_uv(ouv, ny, m1, du, dv);
        en.x = 2.0f*du - ouv[3*m2];
        en.y = 2.0f*dv - ouv[3*m2+1];
        en.z = ouv[3*m2+2];
        float duo, dvo; dummy_uv(ouv_old, ny, m1, duo, dvo);
        eox = 2.0f*duo - ouv_old[3*m2];
        eoy = 2.0f*dvo - ouv_old[3*m2+1];
    } else if (je == EY - 1 && ie >= 1 && ie <= EX - 2) {  // top ghost: WALL
        int m1 = eidx(EY - 2, ie), m2 = eidx(EY - 3, ie);
        float du, dv; dummy_uv(ouv, ny, m1, du, dv);
        en.x = 2.0f*du - ouv[3*m2];
        en.y = 2.0f*dv - ouv[3*m2+1];
        en.z = ouv[3*m2+2];
        float duo, dvo; dummy_uv(ouv_old, ny, m1, duo, dvo);
        eox = 2.0f*duo - ouv_old[3*m2];
        eoy = 2.0f*dvo - ouv_old[3*m2+1];
    } else {
        int mm = eidx(je, ie);
        en.x = ouv[3*mm]; en.y = ouv[3*mm+1]; en.z = ouv[3*mm+2];
        eox = ouv_old[3*mm]; eoy = ouv_old[3*mm+1];
    }
    int e = je * EX + ie;
    if (e == PRESS_E) en.z = 0.0f;

    float dxx = ebm[5*e + 0];
    float dxy = ebm[5*e + 1];
    float dex = ebm[5*e + 2];
    float dey = ebm[5*e + 3];
    float Jm  = ebm[5*e + 4];
    float rJ  = __fdividef(1.0f, Jm);
    float pq  = en.z * rJ;

    Derived d;
    d.eu = en.x; d.ev = en.y; d.ep = en.z; d.eou = eox; d.eov = eoy;
    d.U  = (en.x*dxx + en.y*dxy) * rJ;
    d.V  = (en.x*dex + en.y*dey) * rJ;
    d.Uo = (eox*dxx + eoy*dxy) * rJ;
    d.Vo = (eox*dex + eoy*dey) * rJ;
    d.a11 = (dxx*dxx + dxy*dxy) * rJ;
    d.a22 = (dex*dex + dey*dey) * rJ;
    d.pxx = pq * dxx;
    d.pxy = pq * dxy;
    d.pex = pq * dex;
    d.pey = pq * dey;
    d.rJ  = rJ;
    return d;
}

#define FULLM 0xffffffffu
#define SHL(x) __shfl_up_sync(FULLM, (x), 1)
#define SHR(x) __shfl_down_sync(FULLM, (x), 1)

__device__ __forceinline__ void stencil_store(
    const Derived& m, const Derived& c, const Derived& p,
    int jo, int io, bool wr,
    float cc, float cn, float co, float ucv, float pcv, float dcv, float rdt,
    float* __restrict__ out)
{
    float UL = SHL(c.U),   UR = SHR(c.U);
    float euL = SHL(c.eu), euR = SHR(c.eu);
    float evL = SHL(c.ev), evR = SHR(c.ev);
    float epL = SHL(c.ep), epR = SHR(c.ep);
    float ouL = SHL(c.eou), ouR = SHR(c.eou);
    float ovL = SHL(c.eov), ovR = SHR(c.eov);
    float UoL = SHL(c.Uo), UoR = SHR(c.Uo);
    float a11L = SHL(c.a11), a11R = SHR(c.a11);
    float pxxL = SHL(c.pxx), pxxR = SHR(c.pxx);
    float pxyL = SHL(c.pxy), pxyR = SHR(c.pxy);
    float eumL = SHL(m.eu), eumR = SHR(m.eu);
    float eupL = SHL(p.eu), eupR = SHR(p.eu);
    float evmL = SHL(m.ev), evmR = SHR(m.ev);
    float evpL = SHL(p.ev), evpR = SHR(p.ev);
    float epmL = SHL(m.ep), epmR = SHR(m.ep);
    float eppL = SHL(p.ep), eppR = SHR(p.ep);

    // continuity
    float loss = 0.5f * ((UR - UL) + (p.V - m.V)) * cc;

    // convection (new)
    float cnu = 0.25f * ((c.eu + euR) * (c.U + UR) - (euL + c.eu) * (UL + c.U))
              + 0.25f * ((c.eu + p.eu) * (c.V + p.V) - (m.eu + c.eu) * (m.V + c.V));
    float cnv = 0.25f * ((c.ev + evR) * (c.U + UR) - (evL + c.ev) * (UL + c.U))
              + 0.25f * ((c.ev + p.ev) * (c.V + p.V) - (m.ev + c.ev) * (m.V + c.V));

    // convection (old)
    float cou = 0.25f * ((c.eou + ouR) * (c.Uo + UoR) - (ouL + c.eou) * (UoL + c.Uo))
              + 0.25f * ((c.eou + p.eou) * (c.Vo + p.Vo) - (m.eou + c.eou) * (m.Vo + c.Vo));
    float cov = 0.25f * ((c.eov + ovR) * (c.Uo + UoR) - (ovL + c.eov) * (UoL + c.Uo))
              + 0.25f * ((c.eov + p.eov) * (c.Vo + p.Vo) - (m.eov + c.eov) * (m.Vo + c.Vo));

    // diffusion (new)
    float difu = 0.5f * ((c.a11 + a11R) * (euR - c.eu) - (a11L + c.a11) * (c.eu - euL))
               + 0.5f * ((c.a22 + p.a22) * (p.eu - c.eu) - (m.a22 + c.a22) * (c.eu - m.eu));
    float difv = 0.5f * ((c.a11 + a11R) * (evR - c.ev) - (a11L + c.a11) * (c.ev - evL))
               + 0.5f * ((c.a22 + p.a22) * (p.ev - c.ev) - (m.a22 + c.a22) * (c.ev - m.ev));

    // pressure gradient
    float gPx = 0.5f * (pxxR - pxxL) + 0.5f * (p.pex - m.pex);
    float gPy = 0.5f * (p.pey - m.pey) + 0.5f * (pxyR - pxyL);

    // unsteady (J_o == Jm at interior)
    float inv = c.rJ * rdt;
    float momu = ucv * (c.eu - c.eou) * inv + cn * cnu + co * cou + pcv * gPx - dcv * difu;
    float momv = ucv * (c.ev - c.eov) * inv + cn * cnv + co * cov + pcv * gPy - dcv * difv;

    // uvp_to_vis: (1-2-1)^2 / 16 binomial
    const float swt = 1.0f / 16.0f;
    float visu = swt * (4.0f*c.eu + 2.0f*(euL + euR + m.eu + p.eu) + (eumL + eumR + eupL + eupR));
    float visv = swt * (4.0f*c.ev + 2.0f*(evL + evR + m.ev + p.ev) + (evmL + evmR + evpL + evpR));
    float visp = swt * (4.0f*c.ep + 2.0f*(epL + epR + m.ep + p.ep) + (epmL + epmR + eppL + eppR));

    if (wr) {
        int o = jo * NXg + io;
        out[o]          = loss;
        out[NN + o]     = momu;
        out[2*NN + o]   = momv;
        out[3*NN + 3*o]     = visu;
        out[3*NN + 3*o + 1] = visv;
        out[3*NN + 3*o + 2] = visp;
    }
}

__global__ void __launch_bounds__(BLK, 4)
fused_kernel(const float* __restrict__ ouv,
             const float* __restrict__ ouv_old,
             const float* __restrict__ ny,
             const float* __restrict__ ebm,
             const float* __restrict__ dtg,
             const float* __restrict__ theta,
             const float* __restrict__ relp,
             float* __restrict__ out)
{
    const int gtid = blockIdx.x * BLK + threadIdx.x;
    const int wid  = gtid >> 5;
    const int lane = gtid & 31;

    const int strip = wid % NSTRIP;
    const int chunk = wid / NSTRIP;

    int ie = strip * 30 + lane;
    if (ie > EX - 1) ie = EX - 1;
    const int io  = ie - 1;
    const int jo0 = chunk * H;

    const float rdt   = __fdividef(1.0f, __ldg(dtg));
    const float ucv   = __ldg(theta + 0);
    const float cc    = __ldg(theta + 1);
    const float convc = __ldg(theta + 2);
    const float pcv   = __ldg(theta + 3);
    const float dcv   = __ldg(theta + 4);
    const float relax = __ldg(relp);
    const float cn = convc * (1.0f - relax);
    const float co = convc * relax;

    const bool wr_lane = (lane >= 1) && (lane <= 30) && (io < NXg);

    Derived w0 = load_row(ouv, ouv_old, ny, ebm, jo0,     ie);
    Derived w1 = load_row(ouv, ouv_old, ny, ebm, jo0 + 1, ie);
    Derived w2;

    // H=16 rows: 5 x (3 rows) + 1 epilogue row. ext rows jo0+2 .. jo0+17 <= 1025.
    for (int jb = 0; jb < 15; jb += 3) {
        w2 = load_row(ouv, ouv_old, ny, ebm, jo0 + jb + 2, ie);
        stencil_store(w0, w1, w2, jo0 + jb,     io, wr_lane, cc, cn, co, ucv, pcv, dcv, rdt, out);
        w0 = load_row(ouv, ouv_old, ny, ebm, jo0 + jb + 3, ie);
        stencil_store(w1, w2, w0, jo0 + jb + 1, io, wr_lane, cc, cn, co, ucv, pcv, dcv, rdt, out);
        w1 = load_row(ouv, ouv_old, ny, ebm, jo0 + jb + 4, ie);
        stencil_store(w2, w0, w1, jo0 + jb + 2, io, wr_lane, cc, cn, co, ucv, pcv, dcv, rdt, out);
    }
    // epilogue: output row jo0+15 (ext rows jo0+15, jo0+16, jo0+17)
    w2 = load_row(ouv, ouv_old, ny, ebm, jo0 + 17, ie);
    stencil_store(w0, w1, w2, jo0 + 15, io, wr_lane, cc, cn, co, ucv, pcv, dcv, rdt, out);
}

extern "C" void kernel_launch(void* const* d_in, const int* in_sizes, int n_in,
                              void* d_out, int out_size) {
    const float* ouv     = (const float*)d_in[0];
    const float* ouv_old = (const float*)d_in[1];
    const float* ny      = (const float*)d_in[2];
    // d_in[3] (obm) unused: obm == ebm[interior]
    const float* ebm     = (const float*)d_in[4];
    const float* dtg     = (const float*)d_in[5];
    const float* theta   = (const float*)d_in[6];
    const float* relp    = (const float*)d_in[7];
    float* out = (float*)d_out;

    fused_kernel<<<GRID, BLK>>>(ouv, ouv_old, ny, ebm, dtg, theta, relp, out);
}